// round 14
// baseline (speedup 1.0000x reference)
#include <cuda_runtime.h>
#include <cuda_bf16.h>
#include <math.h>
#include <stdint.h>

#define KK 4
#define BB 64
#define SS 50
#define DD 256
#define VV 40000
#define HH 4
#define DHD 64
#define BS (BB*SS)          // 3200
#define BSD (BS*DD)         // 819200
#define FFD (4*DD)          // 1024
#define NEGV (-1e9f)
#define SCL 0.125f          // 1/sqrt(64)

// -------------------- scratch (device globals, no allocation) ----------------
__device__ __align__(16) float g_h[KK*BSD];      // h_keys accumulators (fp32)
__device__ __align__(16) float g_q[KK*BSD];
__device__ __align__(16) float g_k[KK*BSD];
__device__ __align__(16) float g_v[KK*BSD];
// bf16 hi/lo activation buffers
__device__ __align__(16) __nv_bfloat16 g_xh[KK*BSD], g_xl[KK*BSD];
__device__ __align__(16) __nv_bfloat16 g_oh[KK*BSD], g_ol[KK*BSD];
__device__ __align__(16) __nv_bfloat16 g_ffh[(size_t)KK*BS*FFD], g_ffl[(size_t)KK*BS*FFD];
// bf16 hi/lo weights (converted once per launch)
__device__ __align__(16) __nv_bfloat16 g_wqh[KK*DD*DD], g_wql[KK*DD*DD];
__device__ __align__(16) __nv_bfloat16 g_wkh[KK*DD*DD], g_wkl[KK*DD*DD];
__device__ __align__(16) __nv_bfloat16 g_wvh[KK*DD*DD], g_wvl[KK*DD*DD];
__device__ __align__(16) __nv_bfloat16 g_woh[KK*DD*DD], g_wol[KK*DD*DD];
__device__ __align__(16) __nv_bfloat16 g_w1h[KK*DD*FFD], g_w1l[KK*DD*FFD];
__device__ __align__(16) __nv_bfloat16 g_w2h[KK*FFD*DD], g_w2l[KK*FFD*DD];

__device__ __forceinline__ float warp_sum(float v) {
    #pragma unroll
    for (int o = 16; o; o >>= 1) v += __shfl_xor_sync(0xffffffffu, v, o);
    return v;
}
__device__ __forceinline__ float warp_max(float v) {
    #pragma unroll
    for (int o = 16; o; o >>= 1) v = fmaxf(v, __shfl_xor_sync(0xffffffffu, v, o));
    return v;
}
__device__ __forceinline__ float gelu_f(float x) {
    float x3 = x * x * x;
    return 0.5f * x * (1.0f + tanhf(0.7978845608028654f * (x + 0.044715f * x3)));
}
__device__ __forceinline__ uint32_t packb(__nv_bfloat16 lo, __nv_bfloat16 hi) {
    __nv_bfloat162 t = __halves2bfloat162(lo, hi);
    return *(uint32_t*)&t;
}
__device__ __forceinline__ void split_bf16(float x, __nv_bfloat16& h, __nv_bfloat16& l) {
    h = __float2bfloat16(x);
    l = __float2bfloat16(x - __bfloat162float(h));
}
// split a float4 and store 4 hi + 4 lo bf16 (8B each)
__device__ __forceinline__ void split_store4(__nv_bfloat16* hp, __nv_bfloat16* lp,
                                             size_t off, float4 v) {
    __nv_bfloat16 h0,l0,h1,l1,h2,l2,h3,l3;
    split_bf16(v.x,h0,l0); split_bf16(v.y,h1,l1);
    split_bf16(v.z,h2,l2); split_bf16(v.w,h3,l3);
    *(uint2*)(hp + off) = make_uint2(packb(h0,h1), packb(h2,h3));
    *(uint2*)(lp + off) = make_uint2(packb(l0,l1), packb(l2,l3));
}
__device__ __forceinline__ void mma_bf16(float d[4], const uint32_t a[4],
                                         uint32_t b0, uint32_t b1) {
    asm volatile(
        "mma.sync.aligned.m16n8k16.row.col.f32.bf16.bf16.f32 "
        "{%0,%1,%2,%3}, {%4,%5,%6,%7}, {%8,%9}, {%0,%1,%2,%3};"
        : "+f"(d[0]), "+f"(d[1]), "+f"(d[2]), "+f"(d[3])
        : "r"(a[0]), "r"(a[1]), "r"(a[2]), "r"(a[3]), "r"(b0), "r"(b1));
}
#define LDSM4(r, a) \
    asm volatile("ldmatrix.sync.aligned.m8n8.x4.shared.b16 {%0,%1,%2,%3}, [%4];" \
        : "=r"((r)[0]), "=r"((r)[1]), "=r"((r)[2]), "=r"((r)[3]) : "r"(a))
#define LDSM4T(r, a) \
    asm volatile("ldmatrix.sync.aligned.m8n8.x4.trans.shared.b16 {%0,%1,%2,%3}, [%4];" \
        : "=r"((r)[0]), "=r"((r)[1]), "=r"((r)[2]), "=r"((r)[3]) : "r"(a))
#define CP_ASYNC16(dst, src) \
    asm volatile("cp.async.cg.shared.global [%0], [%1], 16;" :: "r"(dst), "l"(src))
#define CP_COMMIT() asm volatile("cp.async.commit_group;" ::: "memory")
#define CP_WAIT1()  asm volatile("cp.async.wait_group 1;" ::: "memory")
#define CP_WAIT0()  asm volatile("cp.async.wait_group 0;" ::: "memory")

// ---------- weight fp32 -> bf16 hi/lo conversion (float4 vectorized) ---------
__global__ void wconv_kernel(const float* __restrict__ Wq, const float* __restrict__ Wk,
                             const float* __restrict__ Wv, const float* __restrict__ Wo,
                             const float* __restrict__ W1, const float* __restrict__ W2) {
    int idx = blockIdx.x * blockDim.x + threadIdx.x;
    int stride = gridDim.x * blockDim.x;
    const int NW4 = KK * DD * DD / 4;
    const int NF4 = KK * DD * FFD / 4;
    for (int i = idx; i < NW4; i += stride)
        split_store4(g_wqh, g_wql, (size_t)i * 4, ((const float4*)Wq)[i]);
    for (int i = idx; i < NW4; i += stride)
        split_store4(g_wkh, g_wkl, (size_t)i * 4, ((const float4*)Wk)[i]);
    for (int i = idx; i < NW4; i += stride)
        split_store4(g_wvh, g_wvl, (size_t)i * 4, ((const float4*)Wv)[i]);
    for (int i = idx; i < NW4; i += stride)
        split_store4(g_woh, g_wol, (size_t)i * 4, ((const float4*)Wo)[i]);
    for (int i = idx; i < NF4; i += stride)
        split_store4(g_w1h, g_w1l, (size_t)i * 4, ((const float4*)W1)[i]);
    for (int i = idx; i < NF4; i += stride)
        split_store4(g_w2h, g_w2l, (size_t)i * 4, ((const float4*)W2)[i]);
}

// ------- local aggregator + alias distribute + LN1, fused; batched over k ----
// grid (BB, KK); dyn smem: hg[50*256] | a[4*256] | alpha[50*50]  (65.3 KB)
__global__ void localagg_kernel(const float* __restrict__ emb,
                                const int* __restrict__ items,
                                const int* __restrict__ adj,
                                const float* __restrict__ agg_a,
                                const int* __restrict__ alias,
                                const float* __restrict__ ln1g,
                                const float* __restrict__ ln1b,
                                float* __restrict__ h_out,
                                __nv_bfloat16* __restrict__ xh,
                                __nv_bfloat16* __restrict__ xl) {
    extern __shared__ float sm[];
    float* sm_hg = sm;               // 12800 floats
    float* sm_a  = sm + 12800;       // 1024
    float* sm_al = sm + 13824;       // 2500
    int b = blockIdx.x;
    int key = blockIdx.y;
    int tid = threadIdx.x;
    const float* emb_k = emb + (size_t)key * VV * DD;
    const int* items_k = items + (size_t)key * BS + (size_t)b * SS;
    for (int t = tid; t < SS * DD; t += 256) {
        int s = t >> 8, d = t & 255;
        int it = items_k[s];
        sm_hg[t] = emb_k[(size_t)it * DD + d];
    }
    for (int t = tid; t < 4 * DD; t += 256)
        sm_a[t] = agg_a[(size_t)key * 4 * DD + t];
    __syncthreads();

    int w = tid >> 5, lane = tid & 31;
    for (int p = w; p < SS * SS; p += 8) {
        int i = p / SS, j = p % SS;
        int r = adj[(size_t)b * SS * SS + p];
        float val = NEGV;
        if (r != 0) {
            const float4* hi4 = (const float4*)(sm_hg + i * DD);
            const float4* hj4 = (const float4*)(sm_hg + j * DD);
            const float4* ar4 = (const float4*)(sm_a + (r - 1) * DD);
            float acc = 0.0f;
            #pragma unroll
            for (int t = 0; t < 2; t++) {
                int idx = lane + t * 32;
                float4 a = hi4[idx], bb = hj4[idx], c = ar4[idx];
                acc = fmaf(a.x * bb.x, c.x, acc);
                acc = fmaf(a.y * bb.y, c.y, acc);
                acc = fmaf(a.z * bb.z, c.z, acc);
                acc = fmaf(a.w * bb.w, c.w, acc);
            }
            acc = warp_sum(acc);
            val = (acc >= 0.0f) ? acc : 0.2f * acc;   // leaky_relu 0.2
        }
        if (lane == 0) sm_al[p] = val;
    }
    __syncthreads();
    for (int i = w; i < SS; i += 8) {
        float v0 = (lane < SS) ? sm_al[i * SS + lane] : -INFINITY;
        float v1 = (lane + 32 < SS) ? sm_al[i * SS + lane + 32] : -INFINITY;
        float m = warp_max(fmaxf(v0, v1));
        float e0 = (lane < SS) ? expf(v0 - m) : 0.0f;
        float e1 = (lane + 32 < SS) ? expf(v1 - m) : 0.0f;
        float s = warp_sum(e0 + e1);
        float inv = 1.0f / s;
        if (lane < SS) sm_al[i * SS + lane] = e0 * inv;
        if (lane + 32 < SS) sm_al[i * SS + lane + 32] = e1 * inv;
    }
    __syncthreads();
    // alias distribute + on-the-fly h_local + LN1: warp per sequence position
    const float4* g1 = (const float4*)(ln1g + (size_t)key * DD);
    const float4* b1 = (const float4*)(ln1b + (size_t)key * DD);
    for (int s = w; s < SS; s += 8) {
        int row = alias[(size_t)b * SS + s];
        const float* al = sm_al + row * SS;
        float4 v0 = make_float4(0.f, 0.f, 0.f, 0.f);
        float4 v1 = make_float4(0.f, 0.f, 0.f, 0.f);
        #pragma unroll 10
        for (int j = 0; j < SS; j++) {
            float a = al[j];
            float4 h0 = ((const float4*)(sm_hg + j * DD))[lane];
            float4 h1 = ((const float4*)(sm_hg + j * DD))[lane + 32];
            v0.x = fmaf(a, h0.x, v0.x); v0.y = fmaf(a, h0.y, v0.y);
            v0.z = fmaf(a, h0.z, v0.z); v0.w = fmaf(a, h0.w, v0.w);
            v1.x = fmaf(a, h1.x, v1.x); v1.y = fmaf(a, h1.y, v1.y);
            v1.z = fmaf(a, h1.z, v1.z); v1.w = fmaf(a, h1.w, v1.w);
        }
        float sum = v0.x + v0.y + v0.z + v0.w + v1.x + v1.y + v1.z + v1.w;
        float sq  = v0.x*v0.x + v0.y*v0.y + v0.z*v0.z + v0.w*v0.w
                  + v1.x*v1.x + v1.y*v1.y + v1.z*v1.z + v1.w*v1.w;
        sum = warp_sum(sum);
        sq  = warp_sum(sq);
        float mean = sum * (1.0f / DD);
        float var = fmaxf(sq * (1.0f / DD) - mean * mean, 0.0f);
        float inv = rsqrtf(var + 1e-5f);
        size_t dst = (size_t)key * BSD + ((size_t)b * SS + s) * DD;
        float4 gv0 = g1[lane], gv1 = g1[lane + 32];
        float4 bv0 = b1[lane], bv1 = b1[lane + 32];
        float4 x0, x1;
        x0.x = (v0.x - mean) * inv * gv0.x + bv0.x;
        x0.y = (v0.y - mean) * inv * gv0.y + bv0.y;
        x0.z = (v0.z - mean) * inv * gv0.z + bv0.z;
        x0.w = (v0.w - mean) * inv * gv0.w + bv0.w;
        x1.x = (v1.x - mean) * inv * gv1.x + bv1.x;
        x1.y = (v1.y - mean) * inv * gv1.y + bv1.y;
        x1.z = (v1.z - mean) * inv * gv1.z + bv1.z;
        x1.w = (v1.w - mean) * inv * gv1.w + bv1.w;
        ((float4*)(h_out + dst))[lane] = v0;
        ((float4*)(h_out + dst))[lane + 32] = v1;
        split_store4(xh, xl, dst + lane * 4, x0);
        split_store4(xh, xl, dst + 128 + lane * 4, x1);
    }
}

// -------------------- LN2: warp per row, 8 rows per block --------------------
__global__ void ln2_kernel(const float* __restrict__ in,
                           const float* __restrict__ g,
                           const float* __restrict__ bta,
                           __nv_bfloat16* __restrict__ xh,
                           __nv_bfloat16* __restrict__ xl) {
    int gr = blockIdx.x * 8 + (threadIdx.x >> 5);
    int lane = threadIdx.x & 31;
    int key = gr / BS;
    const float4* src = (const float4*)(in + (size_t)gr * DD);
    float4 v0 = src[lane];
    float4 v1 = src[lane + 32];
    float sum = v0.x + v0.y + v0.z + v0.w + v1.x + v1.y + v1.z + v1.w;
    float sq  = v0.x*v0.x + v0.y*v0.y + v0.z*v0.z + v0.w*v0.w
              + v1.x*v1.x + v1.y*v1.y + v1.z*v1.z + v1.w*v1.w;
    sum = warp_sum(sum);
    sq  = warp_sum(sq);
    float mean = sum * (1.0f / DD);
    float var = fmaxf(sq * (1.0f / DD) - mean * mean, 0.0f);
    float inv = rsqrtf(var + 1e-5f);
    const float4* gv = (const float4*)(g + (size_t)key * DD);
    const float4* bv = (const float4*)(bta + (size_t)key * DD);
    float4 g0 = gv[lane], g1 = gv[lane + 32];
    float4 b0 = bv[lane], b1 = bv[lane + 32];
    float4 x0, x1;
    x0.x = (v0.x - mean) * inv * g0.x + b0.x;
    x0.y = (v0.y - mean) * inv * g0.y + b0.y;
    x0.z = (v0.z - mean) * inv * g0.z + b0.z;
    x0.w = (v0.w - mean) * inv * g0.w + b0.w;
    x1.x = (v1.x - mean) * inv * g1.x + b1.x;
    x1.y = (v1.y - mean) * inv * g1.y + b1.y;
    x1.z = (v1.z - mean) * inv * g1.z + b1.z;
    x1.w = (v1.w - mean) * inv * g1.w + b1.w;
    size_t dst = (size_t)gr * DD;
    split_store4(xh, xl, dst + lane * 4, x0);
    split_store4(xh, xl, dst + 128 + lane * 4, x1);
}

// --- 128x128x16 tensor-core GEMM (3xBF16), cp.async 3-stage + ldmatrix -------
#define TBM 128
#define TBN 128
#define TBK 16
#define A_U32S (TBM * 12)
#define B_U32S (TBK * 68)
#define A_SB (A_U32S * 4)
#define B_SB (B_U32S * 4)
#define GEMM_SMEM ((3 * (A_U32S * 2 + B_U32S * 2)) * 4)   // 62976 B

__device__ __forceinline__ void gemm_tile_bf16(
    const __nv_bfloat16* __restrict__ Ah, const __nv_bfloat16* __restrict__ Al,
    const __nv_bfloat16* __restrict__ Bh, const __nv_bfloat16* __restrict__ Bl,
    const float* __restrict__ Res, float* __restrict__ C,
    __nv_bfloat16* __restrict__ Chi, __nv_bfloat16* __restrict__ Clo,
    int N, int Kd, int act) {
    extern __shared__ uint32_t dsm[];
    uint32_t* Ahs = dsm;                    // 3 * A_U32S
    uint32_t* Als = Ahs + 3 * A_U32S;
    uint32_t* Bhs = Als + 3 * A_U32S;       // 3 * B_U32S
    uint32_t* Bls = Bhs + 3 * B_U32S;

    int tid = threadIdx.x;
    int wid = tid >> 5, lane = tid & 31;
    int wm = wid & 1, wn = wid >> 1;          // warp tile 64(m) x 32(n)
    int row0 = blockIdx.y * TBM, col0 = blockIdx.x * TBN;

    int aRow = tid >> 1, aK = (tid & 1) * 8;
    int bK = tid >> 4, bN = (tid & 15) * 8;
    const __nv_bfloat16* gah = Ah + (size_t)(row0 + aRow) * Kd + aK;
    const __nv_bfloat16* gal = Al + (size_t)(row0 + aRow) * Kd + aK;
    const __nv_bfloat16* gbh = Bh + (size_t)bK * N + col0 + bN;
    const __nv_bfloat16* gbl = Bl + (size_t)bK * N + col0 + bN;
    uint32_t s_ah = (uint32_t)__cvta_generic_to_shared(Ahs + aRow * 12 + (aK >> 3) * 4);
    uint32_t s_al = (uint32_t)__cvta_generic_to_shared(Als + aRow * 12 + (aK >> 3) * 4);
    uint32_t s_bh = (uint32_t)__cvta_generic_to_shared(Bhs + bK * 68 + (bN >> 1));
    uint32_t s_bl = (uint32_t)__cvta_generic_to_shared(Bls + bK * 68 + (bN >> 1));

    uint32_t ah_base = (uint32_t)__cvta_generic_to_shared(Ahs);
    uint32_t al_base = (uint32_t)__cvta_generic_to_shared(Als);
    uint32_t bh_base = (uint32_t)__cvta_generic_to_shared(Bhs);
    uint32_t bl_base = (uint32_t)__cvta_generic_to_shared(Bls);
    int a_mrow = 8 * ((lane >> 3) & 1) + (lane & 7);
    uint32_t a_off = (uint32_t)(((wm * 64 + a_mrow) * 12 + (lane >> 4) * 4) * 4);
    int b_krow = 8 * ((lane >> 3) & 1) + (lane & 7);
    uint32_t b_off = (uint32_t)((b_krow * 68 + wn * 16 + (lane >> 4) * 4) * 4);

    int iters = Kd / TBK;
    CP_ASYNC16(s_ah, gah); CP_ASYNC16(s_al, gal);
    CP_ASYNC16(s_bh, gbh); CP_ASYNC16(s_bl, gbl);
    CP_COMMIT();
    if (iters > 1) {
        CP_ASYNC16(s_ah + A_SB, gah + TBK);
        CP_ASYNC16(s_al + A_SB, gal + TBK);
        CP_ASYNC16(s_bh + B_SB, gbh + (size_t)TBK * N);
        CP_ASYNC16(s_bl + B_SB, gbl + (size_t)TBK * N);
        CP_COMMIT();
    }

    float acc[4][4][4] = {};
    for (int i = 0; i < iters; i++) {
        if (i + 1 < iters) CP_WAIT1(); else CP_WAIT0();
        __syncthreads();
        if (i + 2 < iters) {
            int bi2 = (i + 2) % 3;
            size_t ka = (size_t)(i + 2) * TBK;
            CP_ASYNC16(s_ah + bi2 * A_SB, gah + ka);
            CP_ASYNC16(s_al + bi2 * A_SB, gal + ka);
            CP_ASYNC16(s_bh + bi2 * B_SB, gbh + ka * N);
            CP_ASYNC16(s_bl + bi2 * B_SB, gbl + ka * N);
            CP_COMMIT();
        }
        int bi = i % 3;
        uint32_t abuf = (uint32_t)(bi * A_SB), bbuf = (uint32_t)(bi * B_SB);
        uint32_t bh[2][4], bl[2][4];
        #pragma unroll
        for (int p = 0; p < 2; p++) {
            uint32_t bd = b_off + bbuf + (uint32_t)(p * 8 * 4);
            LDSM4T(bh[p], bh_base + bd);
            LDSM4T(bl[p], bl_base + bd);
        }
        #pragma unroll
        for (int mt = 0; mt < 4; mt++) {
            uint32_t ad = a_off + abuf + (uint32_t)(mt * 16 * 12 * 4);
            uint32_t ah4[4], al4[4];
            LDSM4(ah4, ah_base + ad);
            LDSM4(al4, al_base + ad);
            #pragma unroll
            for (int nt = 0; nt < 4; nt++) {
                uint32_t b0h = bh[nt >> 1][(nt & 1) * 2], b1h = bh[nt >> 1][(nt & 1) * 2 + 1];
                uint32_t b0l = bl[nt >> 1][(nt & 1) * 2], b1l = bl[nt >> 1][(nt & 1) * 2 + 1];
                mma_bf16(acc[mt][nt], al4, b0h, b1h);
                mma_bf16(acc[mt][nt], ah4, b0l, b1l);
                mma_bf16(acc[mt][nt], ah4, b0h, b1h);
            }
        }
    }
    int lk = lane & 3, lm = lane >> 2;
    #pragma unroll
    for (int mt = 0; mt < 4; mt++) {
        #pragma unroll
        for (int half = 0; half < 2; half++) {
            int r = row0 + wm * 64 + mt * 16 + lm + half * 8;
            #pragma unroll
            for (int nt = 0; nt < 4; nt++) {
                float v0 = acc[mt][nt][half * 2 + 0];
                float v1 = acc[mt][nt][half * 2 + 1];
                size_t off = (size_t)r * N + col0 + wn * 32 + nt * 8 + 2 * lk;
                if (Res) {
                    float2 rv = *(const float2*)(Res + off);
                    v0 += rv.x; v1 += rv.y;
                }
                if (act == 1) { v0 = gelu_f(v0); v1 = gelu_f(v1); }
                if (Chi) {
                    __nv_bfloat16 h0, l0, h1, l1;
                    split_bf16(v0, h0, l0);
                    split_bf16(v1, h1, l1);
                    *(uint32_t*)(Chi + off) = packb(h0, h1);
                    *(uint32_t*)(Clo + off) = packb(l0, l1);
                } else {
                    *(float2*)(C + off) = make_float2(v0, v1);
                }
            }
        }
    }
}

__global__ void __launch_bounds__(256, 2)
gemm_bat_kernel(const __nv_bfloat16* Ah, const __nv_bfloat16* Al, size_t sA,
                const __nv_bfloat16* Bh, const __nv_bfloat16* Bl, size_t sB,
                const float* Res, size_t sR,
                float* C, size_t sC,
                __nv_bfloat16* Chi, __nv_bfloat16* Clo, size_t sCb,
                int N, int Kd, int act) {
    size_t z = blockIdx.z;
    gemm_tile_bf16(Ah + z * sA, Al + z * sA, Bh + z * sB, Bl + z * sB,
                   Res ? Res + z * sR : nullptr, C ? C + z * sC : nullptr,
                   Chi ? Chi + z * sCb : nullptr, Clo ? Clo + z * sCb : nullptr,
                   N, Kd, act);
}

__global__ void __launch_bounds__(256, 2)
gemm_qkv_kernel(const __nv_bfloat16* xh, const __nv_bfloat16* xl,
                const __nv_bfloat16* wqh, const __nv_bfloat16* wql,
                const __nv_bfloat16* wkh, const __nv_bfloat16* wkl,
                const __nv_bfloat16* wvh, const __nv_bfloat16* wvl,
                float* q, float* k, float* v) {
    int z = blockIdx.z;
    int key = z / 3, m = z - key * 3;
    size_t wo = (size_t)key * DD * DD;
    const __nv_bfloat16* Bh = (m == 0 ? wqh : m == 1 ? wkh : wvh) + wo;
    const __nv_bfloat16* Bl = (m == 0 ? wql : m == 1 ? wkl : wvl) + wo;
    float* C = (m == 0 ? q : m == 1 ? k : v) + (size_t)key * BSD;
    gemm_tile_bf16(xh + (size_t)key * BSD, xl + (size_t)key * BSD,
                   Bh, Bl, nullptr, C, nullptr, nullptr, DD, DD, 0);
}

// ------------- causal MHA v2: Q/K in smem, V via L1, grid (BB, HH, KK) -------
#define ATS 68   // floats per row in smem (17 float4)
__global__ void attn_kernel(const float* __restrict__ q,
                            const float* __restrict__ k,
                            const float* __restrict__ v,
                            __nv_bfloat16* __restrict__ oh,
                            __nv_bfloat16* __restrict__ ol) {
    __shared__ float sq[SS * ATS];
    __shared__ float sk[SS * ATS];
    __shared__ float sp[8 * 64];
    int b = blockIdx.x, h = blockIdx.y;
    size_t kb = (size_t)blockIdx.z * BSD;
    size_t base = kb + (size_t)b * SS * DD + h * DHD;
    for (int t = threadIdx.x; t < SS * 16; t += 256) {
        int s = t >> 4, d4 = t & 15;
        const float4* qp = (const float4*)(q + base + (size_t)s * DD);
        const float4* kp = (const float4*)(k + base + (size_t)s * DD);
        ((float4*)(sq + s * ATS))[d4] = qp[d4];
        ((float4*)(sk + s * ATS))[d4] = kp[d4];
    }
    __syncthreads();
    int w = threadIdx.x >> 5, lane = threadIdx.x & 31;
    for (int i = w; i < SS; i += 8) {
        float sc[2];
        const float4* qi = (const float4*)(sq + i * ATS);
        #pragma unroll
        for (int jj = 0; jj < 2; jj++) {
            int j = lane + jj * 32;
            float val = NEGV;
            if (j < SS && j <= i) {
                const float4* kj = (const float4*)(sk + j * ATS);
                float acc = 0.0f;
                #pragma unroll
                for (int t = 0; t < 16; t++) {
                    float4 a = qi[t], bb = kj[t];
                    acc = fmaf(a.x, bb.x, acc);
                    acc = fmaf(a.y, bb.y, acc);
                    acc = fmaf(a.z, bb.z, acc);
                    acc = fmaf(a.w, bb.w, acc);
                }
                val = acc * SCL;
            }
            sc[jj] = val;
        }
        float m = warp_max(fmaxf(sc[0], sc[1]));
        float e0 = expf(sc[0] - m), e1 = expf(sc[1] - m);
        if (lane + 32 >= SS) e1 = 0.0f;
        float s = warp_sum(e0 + e1);
        float inv = 1.0f / s;
        sp[w * 64 + lane] = e0 * inv;
        if (lane + 32 < 64) sp[w * 64 + 32 + lane] = e1 * inv;
        __syncwarp();
        // AV: lane covers d = 2*lane, 2*lane+1 (float2); V from gmem (L1-hot)
        float2 acc2 = make_float2(0.0f, 0.0f);
        const float2* vbase = (const float2*)(v + base) + lane;
        #pragma unroll 5
        for (int j = 0; j < SS; j++) {
            float a = sp[w * 64 + j];
            float2 vv = __ldg(vbase + j * (DD / 2));
            acc2.x = fmaf(a, vv.x, acc2.x);
            acc2.y = fmaf(a, vv.y, acc2.y);
        }
        size_t oi = base + (size_t)i * DD + 2 * lane;
        __nv_bfloat16 h0, l0, h1, l1;
        split_bf16(acc2.x, h0, l0);
        split_bf16(acc2.y, h1, l1);
        *(uint32_t*)(oh + oi) = packb(h0, h1);
        *(uint32_t*)(ol + oi) = packb(l0, l1);
    }
}

// ---- noisy top-2 gating + combine, warp per row (no block syncs) ------------
// grid = BS/8, 256 threads
__global__ void gate_kernel(const float* __restrict__ emb,
                            const int* __restrict__ ids,
                            const float* __restrict__ Wg,
                            const float* __restrict__ Wn,
                            const float* __restrict__ eps,
                            const float* __restrict__ hk,
                            float* __restrict__ out) {
    int w = threadIdx.x >> 5, lane = threadIdx.x & 31;
    int bs = blockIdx.x * 8 + w;
    int id[KK];
    #pragma unroll
    for (int kk = 0; kk < KK; kk++) id[kk] = ids[(size_t)kk * BS + bs];
    float hx[8];
    #pragma unroll
    for (int t = 0; t < 8; t++) {
        int d = t * 32 + lane;
        float acc = 0.0f;
        #pragma unroll
        for (int kk = 0; kk < KK; kk++)
            acc += emb[(size_t)kk * VV * DD + (size_t)id[kk] * DD + d];
        hx[t] = acc * 0.25f;
    }
    float4 sg4 = make_float4(0.f, 0.f, 0.f, 0.f);
    float4 sn4 = make_float4(0.f, 0.f, 0.f, 0.f);
    #pragma unroll
    for (int t = 0; t < 8; t++) {
        int d = t * 32 + lane;
        float4 wg = ((const float4*)Wg)[d];
        float4 wn = ((const float4*)Wn)[d];
        sg4.x = fmaf(hx[t], wg.x, sg4.x); sg4.y = fmaf(hx[t], wg.y, sg4.y);
        sg4.z = fmaf(hx[t], wg.z, sg4.z); sg4.w = fmaf(hx[t], wg.w, sg4.w);
        sn4.x = fmaf(hx[t], wn.x, sn4.x); sn4.y = fmaf(hx[t], wn.y, sn4.y);
        sn4.z = fmaf(hx[t], wn.z, sn4.z); sn4.w = fmaf(hx[t], wn.w, sn4.w);
    }
    float lgv[KK], nv[KK];
    lgv[0] = warp_sum(sg4.x); lgv[1] = warp_sum(sg4.y);
    lgv[2] = warp_sum(sg4.z); lgv[3] = warp_sum(sg4.w);
    nv[0] = warp_sum(sn4.x); nv[1] = warp_sum(sn4.y);
    nv[2] = warp_sum(sn4.z); nv[3] = warp_sum(sn4.w);
    // all lanes hold the sums (butterfly); compute gates uniformly per lane
    float lg[KK];
    #pragma unroll
    for (int kk = 0; kk < KK; kk++) {
        float noise = nv[kk];
        float sp = (noise > 0.0f) ? (noise + log1pf(expf(-noise)))
                                  : log1pf(expf(noise));
        lg[kk] = lgv[kk] + sp * eps[(size_t)bs * KK + kk];
    }
    int i1 = 0; float v1 = lg[0];
    #pragma unroll
    for (int kk = 1; kk < KK; kk++) if (lg[kk] > v1) { v1 = lg[kk]; i1 = kk; }
    int i2 = -1; float v2 = -INFINITY;
    #pragma unroll
    for (int kk = 0; kk < KK; kk++)
        if (kk != i1 && lg[kk] > v2) { v2 = lg[kk]; i2 = kk; }
    float e2 = expf(v2 - v1);
    float den = 1.0f / (1.0f + e2);
    float sgw[KK];
    #pragma unroll
    for (int kk = 0; kk < KK; kk++) sgw[kk] = 0.0f;
    sgw[i1] = den;
    sgw[i2] = e2 * den;
    #pragma unroll
    for (int t = 0; t < 8; t++) {
        int d = t * 32 + lane;
        float o = 0.0f;
        #pragma unroll
        for (int kk = 0; kk < KK; kk++)
            o += sgw[kk] * hk[(size_t)kk * BSD + (size_t)bs * DD + d];
        out[(size_t)bs * DD + d] = o;
    }
}

// -------------------- launch -------------------------------------------------
extern "C" void kernel_launch(void* const* d_in, const int* in_sizes, int n_in,
                              void* d_out, int out_size) {
    const int*   ids   = (const int*)d_in[0];
    const int*   items = (const int*)d_in[1];
    const int*   adj   = (const int*)d_in[2];
    const int*   alias = (const int*)d_in[3];
    const float* eps   = (const float*)d_in[4];
    const float* emb   = (const float*)d_in[5];
    const float* agg_a = (const float*)d_in[6];
    const float* Wq    = (const float*)d_in[7];
    const float* Wk    = (const float*)d_in[8];
    const float* Wv    = (const float*)d_in[9];
    const float* Wo    = (const float*)d_in[10];
    const float* ln1g  = (const float*)d_in[11];
    const float* ln1b  = (const float*)d_in[12];
    const float* W1    = (const float*)d_in[13];
    const float* W2    = (const float*)d_in[14];
    const float* ln2g  = (const float*)d_in[15];
    const float* ln2b  = (const float*)d_in[16];
    const float* Wg    = (const float*)d_in[17];
    const float* Wn    = (const float*)d_in[18];
    float* out = (float*)d_out;

    float *p_h, *p_q, *p_k, *p_v;
    __nv_bfloat16 *p_xh, *p_xl, *p_oh, *p_ol, *p_ffh, *p_ffl;
    __nv_bfloat16 *p_wqh, *p_wql, *p_wkh, *p_wkl, *p_wvh, *p_wvl;
    __nv_bfloat16 *p_woh, *p_wol, *p_w1h, *p_w1l, *p_w2h, *p_w2l;
    cudaGetSymbolAddress((void**)&p_h,   g_h);
    cudaGetSymbolAddress((void**)&p_q,   g_q);
    cudaGetSymbolAddress((void**)&p_k,   g_k);
    cudaGetSymbolAddress((void**)&p_v,   g_v);
    cudaGetSymbolAddress((void**)&p_xh,  g_xh);
    cudaGetSymbolAddress((void**)&p_xl,  g_xl);
    cudaGetSymbolAddress((void**)&p_oh,  g_oh);
    cudaGetSymbolAddress((void**)&p_ol,  g_ol);
    cudaGetSymbolAddress((void**)&p_ffh, g_ffh);
    cudaGetSymbolAddress((void**)&p_ffl, g_ffl);
    cudaGetSymbolAddress((void**)&p_wqh, g_wqh);
    cudaGetSymbolAddress((void**)&p_wql, g_wql);
    cudaGetSymbolAddress((void**)&p_wkh, g_wkh);
    cudaGetSymbolAddress((void**)&p_wkl, g_wkl);
    cudaGetSymbolAddress((void**)&p_wvh, g_wvh);
    cudaGetSymbolAddress((void**)&p_wvl, g_wvl);
    cudaGetSymbolAddress((void**)&p_woh, g_woh);
    cudaGetSymbolAddress((void**)&p_wol, g_wol);
    cudaGetSymbolAddress((void**)&p_w1h, g_w1h);
    cudaGetSymbolAddress((void**)&p_w1l, g_w1l);
    cudaGetSymbolAddress((void**)&p_w2h, g_w2h);
    cudaGetSymbolAddress((void**)&p_w2l, g_w2l);

    const int smem_agg = (SS * DD + 4 * DD + SS * SS) * sizeof(float);  // 65296
    cudaFuncSetAttribute(localagg_kernel,
                         cudaFuncAttributeMaxDynamicSharedMemorySize, smem_agg);
    cudaFuncSetAttribute(gemm_bat_kernel,
                         cudaFuncAttributeMaxDynamicSharedMemorySize, GEMM_SMEM);
    cudaFuncSetAttribute(gemm_qkv_kernel,
                         cudaFuncAttributeMaxDynamicSharedMemorySize, GEMM_SMEM);

    const size_t sW  = (size_t)DD * DD;
    const size_t sFF = (size_t)BS * FFD;

    // weight conversion (float4 vectorized)
    wconv_kernel<<<1184, 256>>>(Wq, Wk, Wv, Wo, W1, W2);

    // graph aggregation + alias + LN1, all keys (x emitted as bf16 hi/lo)
    localagg_kernel<<<dim3(BB, KK), 256, smem_agg>>>(
        emb, items, adj, agg_a, alias, ln1g, ln1b, p_h, p_xh, p_xl);

    // QKV for all keys (12 GEMMs in one launch)
    gemm_qkv_kernel<<<dim3(DD / TBN, BS / TBM, KK * 3), 256, GEMM_SMEM>>>(
        p_xh, p_xl, p_wqh, p_wql, p_wkh, p_wkl, p_wvh, p_wvl, p_q, p_k, p_v);

    attn_kernel<<<dim3(BB, HH, KK), 256>>>(p_q, p_k, p_v, p_oh, p_ol);

    // h += O @ Wo   (all keys)
    gemm_bat_kernel<<<dim3(DD / TBN, BS / TBM, KK), 256, GEMM_SMEM>>>(
        p_oh, p_ol, (size_t)BSD, p_woh, p_wol, sW,
        p_h, (size_t)BSD, p_h, (size_t)BSD, nullptr, nullptr, 0, DD, DD, 0);

    // LN2 (all keys, warp per row) -> bf16 hi/lo x
    ln2_kernel<<<(KK * BS) / 8, 256>>>(p_h, ln2g, ln2b, p_xh, p_xl);

    // FFN1: gelu(x @ W1) -> ff (bf16 hi/lo)
    gemm_bat_kernel<<<dim3(FFD / TBN, BS / TBM, KK), 256, GEMM_SMEM>>>(
        p_xh, p_xl, (size_t)BSD, p_w1h, p_w1l, (size_t)DD * FFD,
        nullptr, 0, nullptr, 0, p_ffh, p_ffl, sFF, FFD, DD, 1);

    // FFN2: h += ff @ W2
    gemm_bat_kernel<<<dim3(DD / TBN, BS / TBM, KK), 256, GEMM_SMEM>>>(
        p_ffh, p_ffl, sFF, p_w2h, p_w2l, (size_t)FFD * DD,
        p_h, (size_t)BSD, p_h, (size_t)BSD, nullptr, nullptr, 0, DD, FFD, 0);

    // gating (fused h_seq gather, warp per row) + combine
    gate_kernel<<<BS / 8, 256>>>(emb, ids, Wg, Wn, eps, p_h, out);
}

// round 15
// speedup vs baseline: 1.1037x; 1.1037x over previous
#include <cuda_runtime.h>
#include <cuda_bf16.h>
#include <math.h>
#include <stdint.h>

#define KK 4
#define BB 64
#define SS 50
#define DD 256
#define VV 40000
#define HH 4
#define DHD 64
#define BS (BB*SS)          // 3200
#define BSD (BS*DD)         // 819200
#define FFD (4*DD)          // 1024
#define NEGV (-1e9f)
#define SCL 0.125f          // 1/sqrt(64)

// -------------------- scratch (device globals, no allocation) ----------------
__device__ __align__(16) float g_h[KK*BSD];      // h_keys accumulators
__device__ __align__(16) float g_x[KK*BSD];
__device__ __align__(16) float g_q[KK*BSD];
__device__ __align__(16) float g_k[KK*BSD];
__device__ __align__(16) float g_v[KK*BSD];
__device__ __align__(16) float g_o[KK*BSD];
__device__ __align__(16) float g_ff[(size_t)KK*BS*FFD];

__device__ __forceinline__ float warp_sum(float v) {
    #pragma unroll
    for (int o = 16; o; o >>= 1) v += __shfl_xor_sync(0xffffffffu, v, o);
    return v;
}
__device__ __forceinline__ float warp_max(float v) {
    #pragma unroll
    for (int o = 16; o; o >>= 1) v = fmaxf(v, __shfl_xor_sync(0xffffffffu, v, o));
    return v;
}
__device__ __forceinline__ float gelu_f(float x) {
    float x3 = x * x * x;
    return 0.5f * x * (1.0f + tanhf(0.7978845608028654f * (x + 0.044715f * x3)));
}
__device__ __forceinline__ uint32_t packb(__nv_bfloat16 lo, __nv_bfloat16 hi) {
    __nv_bfloat162 t = __halves2bfloat162(lo, hi);
    return *(uint32_t*)&t;
}
__device__ __forceinline__ void split_bf16(float x, __nv_bfloat16& h, __nv_bfloat16& l) {
    h = __float2bfloat16(x);
    l = __float2bfloat16(x - __bfloat162float(h));
}
__device__ __forceinline__ void mma_bf16(float d[4], const uint32_t a[4],
                                         uint32_t b0, uint32_t b1) {
    asm volatile(
        "mma.sync.aligned.m16n8k16.row.col.f32.bf16.bf16.f32 "
        "{%0,%1,%2,%3}, {%4,%5,%6,%7}, {%8,%9}, {%0,%1,%2,%3};"
        : "+f"(d[0]), "+f"(d[1]), "+f"(d[2]), "+f"(d[3])
        : "r"(a[0]), "r"(a[1]), "r"(a[2]), "r"(a[3]), "r"(b0), "r"(b1));
}
#define LDSM4(r, a) \
    asm volatile("ldmatrix.sync.aligned.m8n8.x4.shared.b16 {%0,%1,%2,%3}, [%4];" \
        : "=r"((r)[0]), "=r"((r)[1]), "=r"((r)[2]), "=r"((r)[3]) : "r"(a))
#define LDSM4T(r, a) \
    asm volatile("ldmatrix.sync.aligned.m8n8.x4.trans.shared.b16 {%0,%1,%2,%3}, [%4];" \
        : "=r"((r)[0]), "=r"((r)[1]), "=r"((r)[2]), "=r"((r)[3]) : "r"(a))

// ------- local aggregator + alias distribute + LN1, fused; batched over k ----
// grid (BB, KK); dyn smem: hg[50*256] | a[4*256] | alpha[50*50]  (65.3 KB)
__global__ void localagg_kernel(const float* __restrict__ emb,
                                const int* __restrict__ items,
                                const int* __restrict__ adj,
                                const float* __restrict__ agg_a,
                                const int* __restrict__ alias,
                                const float* __restrict__ ln1g,
                                const float* __restrict__ ln1b,
                                float* __restrict__ h_out,
                                float* __restrict__ x_out) {
    extern __shared__ float sm[];
    float* sm_hg = sm;               // 12800 floats
    float* sm_a  = sm + 12800;       // 1024
    float* sm_al = sm + 13824;       // 2500
    int b = blockIdx.x;
    int key = blockIdx.y;
    int tid = threadIdx.x;
    const float* emb_k = emb + (size_t)key * VV * DD;
    const int* items_k = items + (size_t)key * BS + (size_t)b * SS;
    for (int t = tid; t < SS * DD; t += 256) {
        int s = t >> 8, d = t & 255;
        int it = items_k[s];
        sm_hg[t] = emb_k[(size_t)it * DD + d];
    }
    for (int t = tid; t < 4 * DD; t += 256)
        sm_a[t] = agg_a[(size_t)key * 4 * DD + t];
    __syncthreads();

    int w = tid >> 5, lane = tid & 31;
    for (int p = w; p < SS * SS; p += 8) {
        int i = p / SS, j = p % SS;
        int r = adj[(size_t)b * SS * SS + p];
        float val = NEGV;
        if (r != 0) {
            const float4* hi4 = (const float4*)(sm_hg + i * DD);
            const float4* hj4 = (const float4*)(sm_hg + j * DD);
            const float4* ar4 = (const float4*)(sm_a + (r - 1) * DD);
            float acc = 0.0f;
            #pragma unroll
            for (int t = 0; t < 2; t++) {
                int idx = lane + t * 32;
                float4 a = hi4[idx], bb = hj4[idx], c = ar4[idx];
                acc = fmaf(a.x * bb.x, c.x, acc);
                acc = fmaf(a.y * bb.y, c.y, acc);
                acc = fmaf(a.z * bb.z, c.z, acc);
                acc = fmaf(a.w * bb.w, c.w, acc);
            }
            acc = warp_sum(acc);
            val = (acc >= 0.0f) ? acc : 0.2f * acc;   // leaky_relu 0.2
        }
        if (lane == 0) sm_al[p] = val;
    }
    __syncthreads();
    for (int i = w; i < SS; i += 8) {
        float v0 = (lane < SS) ? sm_al[i * SS + lane] : -INFINITY;
        float v1 = (lane + 32 < SS) ? sm_al[i * SS + lane + 32] : -INFINITY;
        float m = warp_max(fmaxf(v0, v1));
        float e0 = (lane < SS) ? expf(v0 - m) : 0.0f;
        float e1 = (lane + 32 < SS) ? expf(v1 - m) : 0.0f;
        float s = warp_sum(e0 + e1);
        float inv = 1.0f / s;
        if (lane < SS) sm_al[i * SS + lane] = e0 * inv;
        if (lane + 32 < SS) sm_al[i * SS + lane + 32] = e1 * inv;
    }
    __syncthreads();
    // alias distribute + on-the-fly h_local + LN1: warp per sequence position
    const float4* g1 = (const float4*)(ln1g + (size_t)key * DD);
    const float4* b1 = (const float4*)(ln1b + (size_t)key * DD);
    for (int s = w; s < SS; s += 8) {
        int row = alias[(size_t)b * SS + s];
        const float* al = sm_al + row * SS;
        float4 v0 = make_float4(0.f, 0.f, 0.f, 0.f);
        float4 v1 = make_float4(0.f, 0.f, 0.f, 0.f);
        #pragma unroll 10
        for (int j = 0; j < SS; j++) {
            float a = al[j];
            float4 h0 = ((const float4*)(sm_hg + j * DD))[lane];
            float4 h1 = ((const float4*)(sm_hg + j * DD))[lane + 32];
            v0.x = fmaf(a, h0.x, v0.x); v0.y = fmaf(a, h0.y, v0.y);
            v0.z = fmaf(a, h0.z, v0.z); v0.w = fmaf(a, h0.w, v0.w);
            v1.x = fmaf(a, h1.x, v1.x); v1.y = fmaf(a, h1.y, v1.y);
            v1.z = fmaf(a, h1.z, v1.z); v1.w = fmaf(a, h1.w, v1.w);
        }
        float sum = v0.x + v0.y + v0.z + v0.w + v1.x + v1.y + v1.z + v1.w;
        float sq  = v0.x*v0.x + v0.y*v0.y + v0.z*v0.z + v0.w*v0.w
                  + v1.x*v1.x + v1.y*v1.y + v1.z*v1.z + v1.w*v1.w;
        sum = warp_sum(sum);
        sq  = warp_sum(sq);
        float mean = sum * (1.0f / DD);
        float var = fmaxf(sq * (1.0f / DD) - mean * mean, 0.0f);
        float inv = rsqrtf(var + 1e-5f);
        size_t dst = (size_t)key * BSD + ((size_t)b * SS + s) * DD;
        float4 gv0 = g1[lane], gv1 = g1[lane + 32];
        float4 bv0 = b1[lane], bv1 = b1[lane + 32];
        float4 x0, x1;
        x0.x = (v0.x - mean) * inv * gv0.x + bv0.x;
        x0.y = (v0.y - mean) * inv * gv0.y + bv0.y;
        x0.z = (v0.z - mean) * inv * gv0.z + bv0.z;
        x0.w = (v0.w - mean) * inv * gv0.w + bv0.w;
        x1.x = (v1.x - mean) * inv * gv1.x + bv1.x;
        x1.y = (v1.y - mean) * inv * gv1.y + bv1.y;
        x1.z = (v1.z - mean) * inv * gv1.z + bv1.z;
        x1.w = (v1.w - mean) * inv * gv1.w + bv1.w;
        ((float4*)(h_out + dst))[lane] = v0;
        ((float4*)(h_out + dst))[lane + 32] = v1;
        ((float4*)(x_out + dst))[lane] = x0;
        ((float4*)(x_out + dst))[lane + 32] = x1;
    }
}

// -------------------- LN2: warp per row, 8 rows per block --------------------
__global__ void ln2_kernel(const float* __restrict__ in,
                           const float* __restrict__ g,
                           const float* __restrict__ bta,
                           float* __restrict__ x) {
    int gr = blockIdx.x * 8 + (threadIdx.x >> 5);
    int lane = threadIdx.x & 31;
    int key = gr / BS;
    const float4* src = (const float4*)(in + (size_t)gr * DD);
    float4 v0 = src[lane];
    float4 v1 = src[lane + 32];
    float sum = v0.x + v0.y + v0.z + v0.w + v1.x + v1.y + v1.z + v1.w;
    float sq  = v0.x*v0.x + v0.y*v0.y + v0.z*v0.z + v0.w*v0.w
              + v1.x*v1.x + v1.y*v1.y + v1.z*v1.z + v1.w*v1.w;
    sum = warp_sum(sum);
    sq  = warp_sum(sq);
    float mean = sum * (1.0f / DD);
    float var = fmaxf(sq * (1.0f / DD) - mean * mean, 0.0f);
    float inv = rsqrtf(var + 1e-5f);
    const float4* gv = (const float4*)(g + (size_t)key * DD);
    const float4* bv = (const float4*)(bta + (size_t)key * DD);
    float4 g0 = gv[lane], g1 = gv[lane + 32];
    float4 b0 = bv[lane], b1 = bv[lane + 32];
    float4 x0, x1;
    x0.x = (v0.x - mean) * inv * g0.x + b0.x;
    x0.y = (v0.y - mean) * inv * g0.y + b0.y;
    x0.z = (v0.z - mean) * inv * g0.z + b0.z;
    x0.w = (v0.w - mean) * inv * g0.w + b0.w;
    x1.x = (v1.x - mean) * inv * g1.x + b1.x;
    x1.y = (v1.y - mean) * inv * g1.y + b1.y;
    x1.z = (v1.z - mean) * inv * g1.z + b1.z;
    x1.w = (v1.w - mean) * inv * g1.w + b1.w;
    ((float4*)(x + (size_t)gr * DD))[lane] = x0;
    ((float4*)(x + (size_t)gr * DD))[lane + 32] = x1;
}

// --- 128x128x16 tensor-core GEMM (3xBF16, ~fp32 accuracy), ldmatrix frags ----
// A smem: [stage][128 rows][12 u32]  (16 bf16 data + 16B pad; 48B stride)
// B smem: [stage][16 k-rows][68 u32] (128 bf16 data + 16B pad; 272B stride)
#define TBM 128
#define TBN 128
#define TBK 16
__device__ __forceinline__ void cvt8_store(float4 x0, float4 x1,
                                           uint32_t* hd, uint32_t* ld) {
    float v[8] = {x0.x, x0.y, x0.z, x0.w, x1.x, x1.y, x1.z, x1.w};
    uint32_t h[4], l[4];
    #pragma unroll
    for (int j = 0; j < 4; j++) {
        __nv_bfloat16 h0, l0, h1, l1;
        split_bf16(v[2 * j], h0, l0);
        split_bf16(v[2 * j + 1], h1, l1);
        h[j] = packb(h0, h1);
        l[j] = packb(l0, l1);
    }
    *(uint4*)hd = make_uint4(h[0], h[1], h[2], h[3]);
    *(uint4*)ld = make_uint4(l[0], l[1], l[2], l[3]);
}

__device__ __forceinline__ void gemm_tile_bf16(const float* __restrict__ A,
                                               const float* __restrict__ Bm,
                                               const float* __restrict__ Res,
                                               float* __restrict__ C,
                                               int N, int Kd, int act) {
    __shared__ __align__(16) uint32_t Ahs[2][TBM][12];
    __shared__ __align__(16) uint32_t Als[2][TBM][12];
    __shared__ __align__(16) uint32_t Bhs[2][TBK][68];
    __shared__ __align__(16) uint32_t Bls[2][TBK][68];

    int tid = threadIdx.x;
    int wid = tid >> 5, lane = tid & 31;
    int wm = wid & 1, wn = wid >> 1;          // warp tile 64(m) x 32(n)
    int row0 = blockIdx.y * TBM, col0 = blockIdx.x * TBN;

    int aRow = tid >> 1, aK = (tid & 1) * 8;
    int bK = tid >> 4, bN = (tid & 15) * 8;
    const float* Aptr = A + (size_t)(row0 + aRow) * Kd + aK;
    const float* Bptr = Bm + (size_t)bK * N + col0 + bN;
    uint32_t* a_h_st = &Ahs[0][aRow][(aK >> 3) * 4];
    uint32_t* a_l_st = &Als[0][aRow][(aK >> 3) * 4];
    uint32_t* b_h_st = &Bhs[0][bK][bN >> 1];
    uint32_t* b_l_st = &Bls[0][bK][bN >> 1];
    const int A_SS = TBM * 12;
    const int B_SS = TBK * 68;

    uint32_t ah_base = (uint32_t)__cvta_generic_to_shared(&Ahs[0][0][0]);
    uint32_t al_base = (uint32_t)__cvta_generic_to_shared(&Als[0][0][0]);
    uint32_t bh_base = (uint32_t)__cvta_generic_to_shared(&Bhs[0][0][0]);
    uint32_t bl_base = (uint32_t)__cvta_generic_to_shared(&Bls[0][0][0]);
    int a_mrow = 8 * ((lane >> 3) & 1) + (lane & 7);
    uint32_t a_off = (uint32_t)(((wm * 64 + a_mrow) * 12 + (lane >> 4) * 4) * 4);
    int b_krow = 8 * ((lane >> 3) & 1) + (lane & 7);
    uint32_t b_off = (uint32_t)((b_krow * 68 + wn * 16 + (lane >> 4) * 4) * 4);

    float4 aL0 = *(const float4*)Aptr;
    float4 aL1 = *(const float4*)(Aptr + 4);
    float4 bL0 = *(const float4*)Bptr;
    float4 bL1 = *(const float4*)(Bptr + 4);
    cvt8_store(aL0, aL1, a_h_st, a_l_st);
    cvt8_store(bL0, bL1, b_h_st, b_l_st);
    __syncthreads();

    float acc[4][4][4] = {};   // [mt][nt][frag]
    int buf = 0;
    for (int k0 = TBK; k0 <= Kd; k0 += TBK) {
        bool has = (k0 < Kd);
        if (has) {
            aL0 = *(const float4*)(Aptr + k0);
            aL1 = *(const float4*)(Aptr + k0 + 4);
            bL0 = *(const float4*)(Bptr + (size_t)k0 * N);
            bL1 = *(const float4*)(Bptr + (size_t)k0 * N + 4);
        }
        uint32_t abuf = (uint32_t)(buf * A_SS * 4);
        uint32_t bbuf = (uint32_t)(buf * B_SS * 4);
        uint32_t bh[2][4], bl[2][4];
        #pragma unroll
        for (int p = 0; p < 2; p++) {
            uint32_t bd = b_off + bbuf + (uint32_t)(p * 8 * 4);
            LDSM4T(bh[p], bh_base + bd);
            LDSM4T(bl[p], bl_base + bd);
        }
        #pragma unroll
        for (int mt = 0; mt < 4; mt++) {
            uint32_t ad = a_off + abuf + (uint32_t)(mt * 16 * 12 * 4);
            uint32_t ah4[4], al4[4];
            LDSM4(ah4, ah_base + ad);
            LDSM4(al4, al_base + ad);
            #pragma unroll
            for (int nt = 0; nt < 4; nt++) {
                uint32_t b0h = bh[nt >> 1][(nt & 1) * 2], b1h = bh[nt >> 1][(nt & 1) * 2 + 1];
                uint32_t b0l = bl[nt >> 1][(nt & 1) * 2], b1l = bl[nt >> 1][(nt & 1) * 2 + 1];
                mma_bf16(acc[mt][nt], al4, b0h, b1h);
                mma_bf16(acc[mt][nt], ah4, b0l, b1l);
                mma_bf16(acc[mt][nt], ah4, b0h, b1h);
            }
        }
        if (has) {
            int nb = buf ^ 1;
            cvt8_store(aL0, aL1, a_h_st + nb * A_SS, a_l_st + nb * A_SS);
            cvt8_store(bL0, bL1, b_h_st + nb * B_SS, b_l_st + nb * B_SS);
            __syncthreads();
            buf = nb;
        }
    }
    // epilogue: c0,c1 -> (row, col 2lk..2lk+1); c2,c3 -> row+8
    int lk = lane & 3, lm = lane >> 2;
    #pragma unroll
    for (int mt = 0; mt < 4; mt++) {
        #pragma unroll
        for (int half = 0; half < 2; half++) {
            int r = row0 + wm * 64 + mt * 16 + lm + half * 8;
            #pragma unroll
            for (int nt = 0; nt < 4; nt++) {
                float v0 = acc[mt][nt][half * 2 + 0];
                float v1 = acc[mt][nt][half * 2 + 1];
                size_t off = (size_t)r * N + col0 + wn * 32 + nt * 8 + 2 * lk;
                if (Res) {
                    float2 rv = *(const float2*)(Res + off);
                    v0 += rv.x; v1 += rv.y;
                }
                if (act == 1) { v0 = gelu_f(v0); v1 = gelu_f(v1); }
                *(float2*)(C + off) = make_float2(v0, v1);
            }
        }
    }
}

__global__ void __launch_bounds__(256, 2)
gemm_bat_kernel(const float* __restrict__ A, size_t sA,
                const float* __restrict__ Bm, size_t sB,
                const float* __restrict__ Res, size_t sR,
                float* __restrict__ C, size_t sC,
                int N, int Kd, int act) {
    size_t z = blockIdx.z;
    gemm_tile_bf16(A + z * sA, Bm + z * sB,
                   Res ? Res + z * sR : nullptr, C + z * sC, N, Kd, act);
}

__global__ void __launch_bounds__(256, 2)
gemm_qkv_kernel(const float* __restrict__ x,
                const float* __restrict__ Wq,
                const float* __restrict__ Wk,
                const float* __restrict__ Wv,
                float* __restrict__ q,
                float* __restrict__ k,
                float* __restrict__ v) {
    int z = blockIdx.z;
    int key = z / 3, m = z - key * 3;
    const float* A = x + (size_t)key * BSD;
    const float* B = (m == 0 ? Wq : m == 1 ? Wk : Wv) + (size_t)key * DD * DD;
    float* C = (m == 0 ? q : m == 1 ? k : v) + (size_t)key * BSD;
    gemm_tile_bf16(A, B, nullptr, C, DD, DD, 0);
}

// ------------- causal MHA, float4 smem, float2 AV, grid (BB, HH, KK) ---------
#define ATS 68   // floats per row in smem (17 float4)
__global__ void attn_kernel(const float* __restrict__ q,
                            const float* __restrict__ k,
                            const float* __restrict__ v,
                            float* __restrict__ o) {
    __shared__ float sq[SS * ATS];
    __shared__ float sk[SS * ATS];
    __shared__ float sv[SS * ATS];
    __shared__ float sp[8 * 64];
    int b = blockIdx.x, h = blockIdx.y;
    size_t kb = (size_t)blockIdx.z * BSD;
    size_t base = kb + (size_t)b * SS * DD + h * DHD;
    for (int t = threadIdx.x; t < SS * 16; t += 256) {
        int s = t >> 4, d4 = t & 15;
        const float4* qp = (const float4*)(q + base + (size_t)s * DD);
        const float4* kp = (const float4*)(k + base + (size_t)s * DD);
        const float4* vp = (const float4*)(v + base + (size_t)s * DD);
        ((float4*)(sq + s * ATS))[d4] = qp[d4];
        ((float4*)(sk + s * ATS))[d4] = kp[d4];
        ((float4*)(sv + s * ATS))[d4] = vp[d4];
    }
    __syncthreads();
    int w = threadIdx.x >> 5, lane = threadIdx.x & 31;
    for (int i = w; i < SS; i += 8) {
        float sc[2];
        const float4* qi = (const float4*)(sq + i * ATS);
        #pragma unroll
        for (int jj = 0; jj < 2; jj++) {
            int j = lane + jj * 32;
            float val = NEGV;
            if (j < SS && j <= i) {
                const float4* kj = (const float4*)(sk + j * ATS);
                float acc = 0.0f;
                #pragma unroll
                for (int t = 0; t < 16; t++) {
                    float4 a = qi[t], bb = kj[t];
                    acc = fmaf(a.x, bb.x, acc);
                    acc = fmaf(a.y, bb.y, acc);
                    acc = fmaf(a.z, bb.z, acc);
                    acc = fmaf(a.w, bb.w, acc);
                }
                val = acc * SCL;
            }
            sc[jj] = val;
        }
        float m = warp_max(fmaxf(sc[0], sc[1]));
        float e0 = expf(sc[0] - m), e1 = expf(sc[1] - m);
        if (lane + 32 >= SS) e1 = 0.0f;
        float s = warp_sum(e0 + e1);
        float inv = 1.0f / s;
        sp[w * 64 + lane] = e0 * inv;
        if (lane + 32 < 64) sp[w * 64 + 32 + lane] = e1 * inv;
        __syncwarp();
        // AV: lane covers d = 2*lane, 2*lane+1 via float2 smem loads
        float2 acc2 = make_float2(0.0f, 0.0f);
        #pragma unroll 10
        for (int j = 0; j < SS; j++) {
            float a = sp[w * 64 + j];
            float2 vv = *(const float2*)(sv + j * ATS + 2 * lane);
            acc2.x = fmaf(a, vv.x, acc2.x);
            acc2.y = fmaf(a, vv.y, acc2.y);
        }
        *(float2*)(o + base + (size_t)i * DD + 2 * lane) = acc2;
    }
}

// ---- noisy top-2 gating + combine, warp per row (no block syncs) ------------
// grid = BS/8, 256 threads
__global__ void gate_kernel(const float* __restrict__ emb,
                            const int* __restrict__ ids,
                            const float* __restrict__ Wg,
                            const float* __restrict__ Wn,
                            const float* __restrict__ eps,
                            const float* __restrict__ hk,
                            float* __restrict__ out) {
    int w = threadIdx.x >> 5, lane = threadIdx.x & 31;
    int bs = blockIdx.x * 8 + w;
    int id[KK];
    #pragma unroll
    for (int kk = 0; kk < KK; kk++) id[kk] = ids[(size_t)kk * BS + bs];
    float hx[8];
    #pragma unroll
    for (int t = 0; t < 8; t++) {
        int d = t * 32 + lane;
        float acc = 0.0f;
        #pragma unroll
        for (int kk = 0; kk < KK; kk++)
            acc += emb[(size_t)kk * VV * DD + (size_t)id[kk] * DD + d];
        hx[t] = acc * 0.25f;
    }
    float4 sg4 = make_float4(0.f, 0.f, 0.f, 0.f);
    float4 sn4 = make_float4(0.f, 0.f, 0.f, 0.f);
    #pragma unroll
    for (int t = 0; t < 8; t++) {
        int d = t * 32 + lane;
        float4 wg = ((const float4*)Wg)[d];
        float4 wn = ((const float4*)Wn)[d];
        sg4.x = fmaf(hx[t], wg.x, sg4.x); sg4.y = fmaf(hx[t], wg.y, sg4.y);
        sg4.z = fmaf(hx[t], wg.z, sg4.z); sg4.w = fmaf(hx[t], wg.w, sg4.w);
        sn4.x = fmaf(hx[t], wn.x, sn4.x); sn4.y = fmaf(hx[t], wn.y, sn4.y);
        sn4.z = fmaf(hx[t], wn.z, sn4.z); sn4.w = fmaf(hx[t], wn.w, sn4.w);
    }
    float lgv[KK], nv[KK];
    lgv[0] = warp_sum(sg4.x); lgv[1] = warp_sum(sg4.y);
    lgv[2] = warp_sum(sg4.z); lgv[3] = warp_sum(sg4.w);
    nv[0] = warp_sum(sn4.x); nv[1] = warp_sum(sn4.y);
    nv[2] = warp_sum(sn4.z); nv[3] = warp_sum(sn4.w);
    float lg[KK];
    #pragma unroll
    for (int kk = 0; kk < KK; kk++) {
        float noise = nv[kk];
        float sp = (noise > 0.0f) ? (noise + log1pf(expf(-noise)))
                                  : log1pf(expf(noise));
        lg[kk] = lgv[kk] + sp * eps[(size_t)bs * KK + kk];
    }
    int i1 = 0; float v1 = lg[0];
    #pragma unroll
    for (int kk = 1; kk < KK; kk++) if (lg[kk] > v1) { v1 = lg[kk]; i1 = kk; }
    int i2 = -1; float v2 = -INFINITY;
    #pragma unroll
    for (int kk = 0; kk < KK; kk++)
        if (kk != i1 && lg[kk] > v2) { v2 = lg[kk]; i2 = kk; }
    float e2 = expf(v2 - v1);
    float den = 1.0f / (1.0f + e2);
    float sgw[KK];
    #pragma unroll
    for (int kk = 0; kk < KK; kk++) sgw[kk] = 0.0f;
    sgw[i1] = den;
    sgw[i2] = e2 * den;
    #pragma unroll
    for (int t = 0; t < 8; t++) {
        int d = t * 32 + lane;
        float o = 0.0f;
        #pragma unroll
        for (int kk = 0; kk < KK; kk++)
            o += sgw[kk] * hk[(size_t)kk * BSD + (size_t)bs * DD + d];
        out[(size_t)bs * DD + d] = o;
    }
}

// -------------------- launch -------------------------------------------------
extern "C" void kernel_launch(void* const* d_in, const int* in_sizes, int n_in,
                              void* d_out, int out_size) {
    const int*   ids   = (const int*)d_in[0];
    const int*   items = (const int*)d_in[1];
    const int*   adj   = (const int*)d_in[2];
    const int*   alias = (const int*)d_in[3];
    const float* eps   = (const float*)d_in[4];
    const float* emb   = (const float*)d_in[5];
    const float* agg_a = (const float*)d_in[6];
    const float* Wq    = (const float*)d_in[7];
    const float* Wk    = (const float*)d_in[8];
    const float* Wv    = (const float*)d_in[9];
    const float* Wo    = (const float*)d_in[10];
    const float* ln1g  = (const float*)d_in[11];
    const float* ln1b  = (const float*)d_in[12];
    const float* W1    = (const float*)d_in[13];
    const float* W2    = (const float*)d_in[14];
    const float* ln2g  = (const float*)d_in[15];
    const float* ln2b  = (const float*)d_in[16];
    const float* Wg    = (const float*)d_in[17];
    const float* Wn    = (const float*)d_in[18];
    float* out = (float*)d_out;

    float *p_h, *p_x, *p_q, *p_k, *p_v, *p_o, *p_ff;
    cudaGetSymbolAddress((void**)&p_h,  g_h);
    cudaGetSymbolAddress((void**)&p_x,  g_x);
    cudaGetSymbolAddress((void**)&p_q,  g_q);
    cudaGetSymbolAddress((void**)&p_k,  g_k);
    cudaGetSymbolAddress((void**)&p_v,  g_v);
    cudaGetSymbolAddress((void**)&p_o,  g_o);
    cudaGetSymbolAddress((void**)&p_ff, g_ff);

    const int smem_agg = (SS * DD + 4 * DD + SS * SS) * sizeof(float);  // 65296
    cudaFuncSetAttribute(localagg_kernel,
                         cudaFuncAttributeMaxDynamicSharedMemorySize, smem_agg);

    const size_t sW = (size_t)DD * DD;
    const size_t sFF = (size_t)BS * FFD;

    // graph aggregation + alias + LN1, all keys at once (h_local never hits gmem)
    localagg_kernel<<<dim3(BB, KK), 256, smem_agg>>>(
        emb, items, adj, agg_a, alias, ln1g, ln1b, p_h, p_x);

    // QKV for all keys (12 GEMMs in one launch)
    gemm_qkv_kernel<<<dim3(DD / TBN, BS / TBM, KK * 3), 256>>>(
        p_x, Wq, Wk, Wv, p_q, p_k, p_v);

    attn_kernel<<<dim3(BB, HH, KK), 256>>>(p_q, p_k, p_v, p_o);

    // h += O @ Wo   (all keys)
    gemm_bat_kernel<<<dim3(DD / TBN, BS / TBM, KK), 256>>>(
        p_o, (size_t)BSD, Wo, sW, p_h, (size_t)BSD, p_h, (size_t)BSD, DD, DD, 0);

    // LN2 (all keys, warp per row)
    ln2_kernel<<<(KK * BS) / 8, 256>>>(p_h, ln2g, ln2b, p_x);

    // FFN1: gelu(x @ W1)  (all keys)
    gemm_bat_kernel<<<dim3(FFD / TBN, BS / TBM, KK), 256>>>(
        p_x, (size_t)BSD, W1, (size_t)DD * FFD, nullptr, 0, p_ff, sFF, FFD, DD, 1);

    // FFN2: h += ff @ W2  (all keys)
    gemm_bat_kernel<<<dim3(DD / TBN, BS / TBM, KK), 256>>>(
        p_ff, sFF, W2, (size_t)FFD * DD, p_h, (size_t)BSD, p_h, (size_t)BSD, DD, FFD, 0);

    // gating (fused h_seq gather, warp per row) + combine
    gate_kernel<<<BS / 8, 256>>>(emb, ids, Wg, Wn, eps, p_h, out);
}